// round 13
// baseline (speedup 1.0000x reference)
#include <cuda_runtime.h>
#include <cstdint>

// Problem dims
#define B_DIM 32
#define S_DIM 2048
#define H_DIM 1024
#define NROWS (B_DIM * S_DIM)   // 65536

// ---------------- device scratch (no allocs allowed) ----------------
__device__ float g_part[16 * NROWS];               // partial scores: 16 planes (nc,wn)
__device__ float g_c[B_DIM * H_DIM];               // hW[b,k] + attn_b[k]
__device__ float g_ctxp[8 * B_DIM * H_DIM];        // context partials: 8 s-chunks
// We pair-packed + tf32-rounded: pair-row p = (h>>3)*4 + (h&3), sel = (h>>2)&1
//   g_WeB[(p*1024 + n)*2 + sel] = rna_tf32(We[n][h])   (float2 {B[k][n], B[k+4][n]})
__device__ float g_WeB[H_DIM * H_DIM];

// ---------------- helpers ----------------
__device__ __forceinline__ uint32_t smem_u32(const void* p) {
    uint32_t a;
    asm("{ .reg .u64 t; cvta.to.shared.u64 t, %1; cvt.u32.u64 %0, t; }"
        : "=r"(a) : "l"(p));
    return a;
}

__device__ __forceinline__ uint32_t f2tf32(float f) {
    uint32_t u;
    asm("cvt.rna.tf32.f32 %0, %1;" : "=r"(u) : "f"(f));
    return u;
}

// single-MUFU tanh (max err ~2^-11; fine vs 1e-3 gate with 1.9e-4 base)
__device__ __forceinline__ float tanh_fast(float x) {
    float y;
    asm("tanh.approx.f32 %0, %1;" : "=f"(y) : "f"(x));
    return y;
}

#define CP_ASYNC16(dst_u32, src_ptr) \
    asm volatile("cp.async.cg.shared.global [%0], [%1], 16;" \
                 :: "r"(dst_u32), "l"(src_ptr) : "memory")

// mbarrier ops
#define MBARRIER_INIT(mbar, count) \
    asm volatile("mbarrier.init.shared.b64 [%0], %1;" \
                 :: "r"((uint32_t)(mbar)), "r"((uint32_t)(count)) : "memory")

#define MBARRIER_ARRIVE(mbar) \
    asm volatile("mbarrier.arrive.shared.b64 _, [%0];" \
                 :: "r"((uint32_t)(mbar)) : "memory")

// arrive fires when this thread's prior cp.asyncs have completed (no count inc)
#define CP_ASYNC_MBAR_ARRIVE(mbar) \
    asm volatile("cp.async.mbarrier.arrive.noinc.shared.b64 [%0];" \
                 :: "r"((uint32_t)(mbar)) : "memory")

#define MBARRIER_WAIT_PARITY(mbar_smem_addr, phase_parity) do { \
    uint32_t _mbar = (uint32_t)(mbar_smem_addr); \
    uint32_t _parity = (uint32_t)(phase_parity); \
    uint32_t _done; \
    asm volatile( \
        "{\n\t" \
        ".reg .pred p;\n\t" \
        "mbarrier.try_wait.parity.acquire.cta.shared::cta.b64 p, [%1], %2;\n\t" \
        "selp.b32 %0, 1, 0, p;\n\t" \
        "}" \
        : "=r"(_done) : "r"(_mbar), "r"(_parity) : "memory"); \
    if (!_done) { \
        asm volatile( \
            "{\n\t" \
            ".reg .pred P1;\n\t" \
            "WAIT_LOOP_%=:\n\t" \
            "mbarrier.try_wait.parity.acquire.cta.shared::cta.b64 P1, [%0], %1, 0x989680;\n\t" \
            "@P1 bra.uni WAIT_DONE_%=;\n\t" \
            "bra.uni WAIT_LOOP_%=;\n\t" \
            "WAIT_DONE_%=:\n\t" \
            "}" \
            :: "r"(_mbar), "r"(_parity) : "memory"); \
    } \
} while (0)

__device__ __forceinline__ void mma_tf32(float d[4], const uint32_t a[4],
                                         const uint32_t b[2]) {
    asm volatile(
        "mma.sync.aligned.m16n8k8.row.col.f32.tf32.tf32.f32 "
        "{%0,%1,%2,%3}, {%4,%5,%6,%7}, {%8,%9}, {%0,%1,%2,%3};"
        : "+f"(d[0]), "+f"(d[1]), "+f"(d[2]), "+f"(d[3])
        : "r"(a[0]), "r"(a[1]), "r"(a[2]), "r"(a[3]), "r"(b[0]), "r"(b[1]));
}

// ---------------- kernel A: transpose + tf32-round + pair-pack We ----------------
__global__ void transpose_we_kernel(const float* __restrict__ attn_w) {
    __shared__ float t[32][33];
    int nb = blockIdx.x * 32, hb = blockIdx.y * 32;
    int x = threadIdx.x, y = threadIdx.y;   // 32 x 8
    #pragma unroll
    for (int j = 0; j < 4; j++)
        t[y + 8 * j][x] = attn_w[(size_t)(nb + y + 8 * j) * (2 * H_DIM) + H_DIM + hb + x];
    __syncthreads();
    #pragma unroll
    for (int j = 0; j < 4; j++) {
        int h = hb + y + 8 * j;
        int n = nb + x;
        int p = (h >> 3) * 4 + (h & 3);
        int sel = (h >> 2) & 1;
        g_WeB[((size_t)p * H_DIM + n) * 2 + sel] = __uint_as_float(f2tf32(t[x][y + 8 * j]));
    }
}

// ---------------- kernel 0: copy hidden half of output ----------------
__global__ void init_kernel(const float* __restrict__ hidden, float* __restrict__ out) {
    int idx = blockIdx.x * 256 + threadIdx.x;          // 0..32767
    int b = idx >> 10;
    int c = idx & 1023;
    out[b * (2 * H_DIM) + H_DIM + c] = hidden[idx];
}

// ---------------- kernel 1: c[b,k] = hidden @ Wh^T + attn_b ----------------
// grid (128 k-chunks, 4 b-groups), block 256 (8 warps). Warp = one k, 8 batches.
__global__ void cvec_kernel(const float* __restrict__ hidden,
                            const float* __restrict__ attn_w,
                            const float* __restrict__ attn_b) {
    __shared__ float hdS[8][H_DIM];
    const int tid = threadIdx.x;
    const int wid = tid >> 5, lane = tid & 31;
    const int k = blockIdx.x * 8 + wid;
    const int b0 = blockIdx.y * 8;
    for (int i = tid; i < 8 * H_DIM; i += 256)
        hdS[i >> 10][i & (H_DIM - 1)] = hidden[(size_t)b0 * H_DIM + i];
    const float* wrow = attn_w + (size_t)k * (2 * H_DIM);   // Wh row k
    float wv[32];
    #pragma unroll
    for (int j = 0; j < 32; j++) wv[j] = wrow[lane + 32 * j];
    float bias = attn_b[k];
    __syncthreads();
    #pragma unroll
    for (int bi = 0; bi < 8; bi++) {
        float s = 0.0f;
        #pragma unroll
        for (int j = 0; j < 32; j++) s = fmaf(wv[j], hdS[bi][lane + 32 * j], s);
        #pragma unroll
        for (int o = 16; o > 0; o >>= 1) s += __shfl_xor_sync(0xffffffffu, s, o);
        if (lane == 0) g_c[(size_t)(b0 + bi) * H_DIM + k] = s + bias;
    }
}

// ---------------- kernel 2: fused tf32 mma.sync GEMM + tanh + v-dot ----------------
// CTA tile: M=128 x N=128, K=1024 (32 iters of KC=32). 4 warps 2x2, tile 64x64.
// 2 CTAs/SM. 3-slot cp.async ring + mbarrier full/empty pipeline.
// B fragments loaded BEFORE A ldmatrix in each ks block (latency ordering).
static constexpr int NKITER = 32;
static constexpr int W_C    = 0;      // words
static constexpr int W_V    = 128;
static constexpr int W_BARS = 256;    // 6 mbarriers: full[0..2], empty[0..2]
static constexpr int W_A    = 272;
static constexpr int STAGE_WORDS = 4096 + 4096;     // 8192
static constexpr int GEMM_SMEM_BYTES = (W_A + 3 * STAGE_WORDS) * 4;   // 99,392

__device__ __forceinline__ uint32_t full_bar(uint32_t smem_base, int s) {
    return smem_base + (W_BARS + 2 * s) * 4;
}
__device__ __forceinline__ uint32_t empty_bar(uint32_t smem_base, int s) {
    return smem_base + (W_BARS + 6 + 2 * s) * 4;
}

__device__ __forceinline__ void load_stage(uint32_t smem_base, int slot,
                                           const float* __restrict__ enc,
                                           const float2* __restrict__ WeB2,
                                           int row0, int kg0, int it, int tid) {
    const int base_w = W_A + slot * STAGE_WORDS;
    const int hbase = it * 32;
    // A: 128 rows x 32 words = 1024 16B chunks, 8 per thread (128 threads)
    #pragma unroll
    for (int j = 0; j < 8; j++) {
        int c = tid + j * 128;
        int m = c >> 3, k0 = (c & 7) * 4;
        uint32_t w = (uint32_t)(base_w + m * 32 + (k0 ^ ((m & 7) * 4)));
        CP_ASYNC16(smem_base + w * 4, enc + (size_t)(row0 + m) * H_DIM + hbase + k0);
    }
    // B: 16 pair-rows x 128 float2 = 1024 16B chunks, 8 per thread
    #pragma unroll
    for (int j = 0; j < 8; j++) {
        int c = tid + j * 128;
        int prow = c >> 6, n0 = (c & 63) * 2;     // float2 index, 2 per chunk
        uint32_t f2i = (uint32_t)(prow * 128 + (n0 ^ (4 * (prow & 3))));
        uint32_t w = (uint32_t)(base_w + 4096) + f2i * 2;
        CP_ASYNC16(smem_base + w * 4,
                   WeB2 + (size_t)(it * 16 + prow) * H_DIM + kg0 + n0);
    }
}

__global__ void __launch_bounds__(128, 2)
gemm_scores_kernel(const float* __restrict__ enc,
                   const float* __restrict__ v_w) {
    extern __shared__ float smw[];
    uint32_t smem_base = smem_u32(smw);
    const int tid = threadIdx.x;
    const int wid = tid >> 5, lane = tid & 31;
    const int q = lane >> 2, t4 = lane & 3;
    const int wm = wid & 1, wn = wid >> 1;          // 2 x 2 warp grid
    const int row0 = blockIdx.y * 128;              // row-block (slow axis)
    const int b = row0 >> 11;
    const int nc = blockIdx.x;                      // n-chunk (fast axis -> L2 A reuse)
    const int kg0 = nc * 128;

    const float2* __restrict__ WeB2 = reinterpret_cast<const float2*>(g_WeB);

    if (tid == 0) {
        #pragma unroll
        for (int s = 0; s < 3; s++) {
            MBARRIER_INIT(full_bar(smem_base, s), 128);
            MBARRIER_INIT(empty_bar(smem_base, s), 128);
        }
    }
    smw[W_C + tid] = g_c[b * H_DIM + kg0 + tid];
    smw[W_V + tid] = v_w[kg0 + tid];
    __syncthreads();

    // prologue: stages 0,1 into slots 0,1 (slots fresh -> no empty wait)
    load_stage(smem_base, 0, enc, WeB2, row0, kg0, 0, tid);
    CP_ASYNC_MBAR_ARRIVE(full_bar(smem_base, 0));
    load_stage(smem_base, 1, enc, WeB2, row0, kg0, 1, tid);
    CP_ASYNC_MBAR_ARRIVE(full_bar(smem_base, 1));

    // accumulators: 4 m-tiles x 8 n-tiles x 4 regs = 128
    float d[4][8][4];
    #pragma unroll
    for (int mt = 0; mt < 4; mt++)
        #pragma unroll
        for (int nt = 0; nt < 8; nt++)
            #pragma unroll
            for (int r = 0; r < 4; r++) d[mt][nt][r] = 0.0f;

    for (int it = 0; it < NKITER; it++) {
        const int slot = it % 3;
        MBARRIER_WAIT_PARITY(full_bar(smem_base, slot), (it / 3) & 1);

        const int bufA = W_A + slot * STAGE_WORDS;
        const float2* bufB = reinterpret_cast<const float2*>(smw + bufA + 4096);

        #pragma unroll
        for (int ks = 0; ks < 4; ks++) {
            // B fragments first (LDS 29-cyc latency gets covered by A ldmatrix)
            const int prow_l = ks * 4 + t4;
            uint32_t bb[8][2];
            #pragma unroll
            for (int nt = 0; nt < 8; nt++) {
                int col = wn * 64 + nt * 8 + q;
                float2 v = bufB[prow_l * 128 + (col ^ (4 * t4))];
                bb[nt][0] = __float_as_uint(v.x);
                bb[nt][1] = __float_as_uint(v.y);
            }
            // A fragments: one ldmatrix.x4 per mt
            uint32_t a[4][4];
            #pragma unroll
            for (int mt = 0; mt < 4; mt++) {
                int m = wm * 64 + mt * 16 + (lane & 15);
                int chk = ks * 2 + (lane >> 4);            // 16B chunk index in row
                uint32_t w = (uint32_t)(bufA + m * 32 + ((chk * 4) ^ ((m & 7) * 4)));
                uint32_t addr = smem_base + w * 4;
                asm volatile(
                    "ldmatrix.sync.aligned.m8n8.x4.shared.b16 {%0,%1,%2,%3}, [%4];"
                    : "=r"(a[mt][0]), "=r"(a[mt][1]), "=r"(a[mt][2]), "=r"(a[mt][3])
                    : "r"(addr));
            }
            #pragma unroll
            for (int mt = 0; mt < 4; mt++)
                #pragma unroll
                for (int nt = 0; nt < 8; nt++)
                    mma_tf32(d[mt][nt], a[mt], bb[nt]);

            // prefetch stage it+2 into slot (it+2)%3 after ks=0's MMAs
            if (ks == 0 && it + 2 < NKITER) {
                const int pslot = (it + 2) % 3;
                if (it >= 1) {
                    MBARRIER_WAIT_PARITY(empty_bar(smem_base, pslot), ((it - 1) / 3) & 1);
                }
                load_stage(smem_base, pslot, enc, WeB2, row0, kg0, it + 2, tid);
                CP_ASYNC_MBAR_ARRIVE(full_bar(smem_base, pslot));
            }
        }
        MBARRIER_ARRIVE(empty_bar(smem_base, slot));
    }

    // Epilogue: partial[plane][r] = sum_{n in warp's half} v[n]*tanh(d + c[n])
    #pragma unroll
    for (int mt = 0; mt < 4; mt++) {
        float s0 = 0.0f, s1 = 0.0f;
        #pragma unroll
        for (int nt = 0; nt < 8; nt++) {
            int n = wn * 64 + nt * 8 + t4 * 2;
            float c0 = smw[W_C + n], c1 = smw[W_C + n + 1];
            float v0 = smw[W_V + n], v1 = smw[W_V + n + 1];
            s0 = fmaf(tanh_fast(d[mt][nt][0] + c0), v0, s0);
            s0 = fmaf(tanh_fast(d[mt][nt][1] + c1), v1, s0);
            s1 = fmaf(tanh_fast(d[mt][nt][2] + c0), v0, s1);
            s1 = fmaf(tanh_fast(d[mt][nt][3] + c1), v1, s1);
        }
        #pragma unroll
        for (int o = 1; o < 4; o <<= 1) {
            s0 += __shfl_xor_sync(0xffffffffu, s0, o);
            s1 += __shfl_xor_sync(0xffffffffu, s1, o);
        }
        if (t4 == 0) {
            int r = row0 + wm * 64 + mt * 16 + q;
            size_t plane = (size_t)(nc * 2 + wn) * NROWS;
            g_part[plane + r] = s0;
            g_part[plane + r + 8] = s1;
        }
    }
}

// ---------------- kernel 3: fold partials + softmax over S per batch ----------------
__global__ void softmax_kernel(float* __restrict__ outw) {
    __shared__ float sh[S_DIM];
    __shared__ float red[256];
    int b = blockIdx.x, tid = threadIdx.x;
    float lmax = -1e30f;
    for (int i = tid; i < S_DIM; i += 256) {
        float v = 0.0f;
        #pragma unroll
        for (int p = 0; p < 16; p++) v += g_part[(size_t)p * NROWS + b * S_DIM + i];
        sh[i] = v;
        lmax = fmaxf(lmax, v);
    }
    red[tid] = lmax;
    __syncthreads();
    for (int s = 128; s > 0; s >>= 1) {
        if (tid < s) red[tid] = fmaxf(red[tid], red[tid + s]);
        __syncthreads();
    }
    float m = red[0];
    __syncthreads();
    float lsum = 0.0f;
    for (int i = tid; i < S_DIM; i += 256) {
        float e = expf(sh[i] - m);
        sh[i] = e;
        lsum += e;
    }
    red[tid] = lsum;
    __syncthreads();
    for (int s = 128; s > 0; s >>= 1) {
        if (tid < s) red[tid] += red[tid + s];
        __syncthreads();
    }
    float inv = 1.0f / red[0];
    for (int i = tid; i < S_DIM; i += 256) outw[b * S_DIM + i] = sh[i] * inv;
}

// ---------------- kernel 4: context partials (atomic-free) ----------------
// grid (32 b, 8 s-chunks of 256), block 256: thread owns float4 (h-chunk).
__global__ void context_kernel(const float* __restrict__ enc,
                               const float* __restrict__ w,
                               float* __restrict__ out_unused) {
    __shared__ float ws[256];
    int b = blockIdx.x, sc = blockIdx.y, tid = threadIdx.x;
    ws[tid] = w[b * S_DIM + sc * 256 + tid];
    __syncthreads();
    const float4* e4 = reinterpret_cast<const float4*>(
        enc + ((size_t)(b * S_DIM + sc * 256)) * H_DIM);
    float ax = 0.f, ay = 0.f, az = 0.f, aw = 0.f;
    #pragma unroll 4
    for (int s = 0; s < 256; s++) {
        float wv = ws[s];
        float4 ev = e4[(size_t)s * 256 + tid];
        ax = fmaf(wv, ev.x, ax); ay = fmaf(wv, ev.y, ay);
        az = fmaf(wv, ev.z, az); aw = fmaf(wv, ev.w, aw);
    }
    float4* cp = reinterpret_cast<float4*>(
        g_ctxp + ((size_t)sc * B_DIM + b) * H_DIM);
    cp[tid] = make_float4(ax, ay, az, aw);
}

// fold 8 context partial planes into the ctx half of out
__global__ void context_fold_kernel(float* __restrict__ out) {
    int idx = blockIdx.x * 256 + threadIdx.x;          // 0..32767 (b*1024+h)
    int b = idx >> 10;
    int h = idx & 1023;
    float s = 0.0f;
    #pragma unroll
    for (int p = 0; p < 8; p++)
        s += g_ctxp[((size_t)p * B_DIM + b) * H_DIM + h];
    out[b * (2 * H_DIM) + h] = s;
}

// ---------------- launcher ----------------
extern "C" void kernel_launch(void* const* d_in, const int* in_sizes, int n_in,
                              void* d_out, int out_size) {
    const float* hidden = (const float*)d_in[0];   // (32, 1024)
    const float* enc    = (const float*)d_in[1];   // (32, 2048, 1024)
    const float* attn_w = (const float*)d_in[2];   // (1024, 2048)
    const float* attn_b = (const float*)d_in[3];   // (1024,)
    const float* v_w    = (const float*)d_in[4];   // (1, 1024)
    float* out = (float*)d_out;                    // [output (32,2048) | attn_w (32,2048,1)]

    cudaFuncSetAttribute(gemm_scores_kernel,
                         cudaFuncAttributeMaxDynamicSharedMemorySize,
                         GEMM_SMEM_BYTES);

    transpose_we_kernel<<<dim3(32, 32), dim3(32, 8)>>>(attn_w);
    init_kernel<<<128, 256>>>(hidden, out);
    cvec_kernel<<<dim3(128, 4), 256>>>(hidden, attn_w, attn_b);
    gemm_scores_kernel<<<dim3(8, 512), 128, GEMM_SMEM_BYTES>>>(enc, v_w);
    softmax_kernel<<<32, 256>>>(out + B_DIM * S_DIM);
    context_kernel<<<dim3(32, 8), 256>>>(enc, out + B_DIM * S_DIM, out);
    context_fold_kernel<<<128, 256>>>(out);
}

// round 14
// speedup vs baseline: 1.0177x; 1.0177x over previous
#include <cuda_runtime.h>
#include <cstdint>

// Problem dims
#define B_DIM 32
#define S_DIM 2048
#define H_DIM 1024
#define NROWS (B_DIM * S_DIM)   // 65536

// ---------------- device scratch (no allocs allowed) ----------------
__device__ float g_part[16 * NROWS];               // partial scores: 16 planes (nc,wn)
__device__ float g_c[B_DIM * H_DIM];               // hW[b,k] + attn_b[k]
// We pair-packed + tf32-rounded: pair-row p = (h>>3)*4 + (h&3), sel = (h>>2)&1
//   g_WeB[(p*1024 + n)*2 + sel] = rna_tf32(We[n][h])   (float2 {B[k][n], B[k+4][n]})
__device__ float g_WeB[H_DIM * H_DIM];

// ---------------- helpers ----------------
__device__ __forceinline__ uint32_t smem_u32(const void* p) {
    uint32_t a;
    asm("{ .reg .u64 t; cvta.to.shared.u64 t, %1; cvt.u32.u64 %0, t; }"
        : "=r"(a) : "l"(p));
    return a;
}

__device__ __forceinline__ uint32_t f2tf32(float f) {
    uint32_t u;
    asm("cvt.rna.tf32.f32 %0, %1;" : "=r"(u) : "f"(f));
    return u;
}

// single-MUFU tanh (max err ~2^-11; fine vs 1e-3 gate with 1.9e-4 base)
__device__ __forceinline__ float tanh_fast(float x) {
    float y;
    asm("tanh.approx.f32 %0, %1;" : "=f"(y) : "f"(x));
    return y;
}

#define CP_ASYNC16(dst_u32, src_ptr) \
    asm volatile("cp.async.cg.shared.global [%0], [%1], 16;" \
                 :: "r"(dst_u32), "l"(src_ptr) : "memory")

// mbarrier ops
#define MBARRIER_INIT(mbar, count) \
    asm volatile("mbarrier.init.shared.b64 [%0], %1;" \
                 :: "r"((uint32_t)(mbar)), "r"((uint32_t)(count)) : "memory")

#define MBARRIER_ARRIVE(mbar) \
    asm volatile("mbarrier.arrive.shared.b64 _, [%0];" \
                 :: "r"((uint32_t)(mbar)) : "memory")

// arrive fires when this thread's prior cp.asyncs have completed (no count inc)
#define CP_ASYNC_MBAR_ARRIVE(mbar) \
    asm volatile("cp.async.mbarrier.arrive.noinc.shared.b64 [%0];" \
                 :: "r"((uint32_t)(mbar)) : "memory")

#define MBARRIER_WAIT_PARITY(mbar_smem_addr, phase_parity) do { \
    uint32_t _mbar = (uint32_t)(mbar_smem_addr); \
    uint32_t _parity = (uint32_t)(phase_parity); \
    uint32_t _done; \
    asm volatile( \
        "{\n\t" \
        ".reg .pred p;\n\t" \
        "mbarrier.try_wait.parity.acquire.cta.shared::cta.b64 p, [%1], %2;\n\t" \
        "selp.b32 %0, 1, 0, p;\n\t" \
        "}" \
        : "=r"(_done) : "r"(_mbar), "r"(_parity) : "memory"); \
    if (!_done) { \
        asm volatile( \
            "{\n\t" \
            ".reg .pred P1;\n\t" \
            "WAIT_LOOP_%=:\n\t" \
            "mbarrier.try_wait.parity.acquire.cta.shared::cta.b64 P1, [%0], %1, 0x989680;\n\t" \
            "@P1 bra.uni WAIT_DONE_%=;\n\t" \
            "bra.uni WAIT_LOOP_%=;\n\t" \
            "WAIT_DONE_%=:\n\t" \
            "}" \
            :: "r"(_mbar), "r"(_parity) : "memory"); \
    } \
} while (0)

__device__ __forceinline__ void mma_tf32(float d[4], const uint32_t a[4],
                                         const uint32_t b[2]) {
    asm volatile(
        "mma.sync.aligned.m16n8k8.row.col.f32.tf32.tf32.f32 "
        "{%0,%1,%2,%3}, {%4,%5,%6,%7}, {%8,%9}, {%0,%1,%2,%3};"
        : "+f"(d[0]), "+f"(d[1]), "+f"(d[2]), "+f"(d[3])
        : "r"(a[0]), "r"(a[1]), "r"(a[2]), "r"(a[3]), "r"(b[0]), "r"(b[1]));
}

// ---------------- kernel A: transpose + tf32-round + pair-pack We ----------------
__global__ void transpose_we_kernel(const float* __restrict__ attn_w) {
    __shared__ float t[32][33];
    int nb = blockIdx.x * 32, hb = blockIdx.y * 32;
    int x = threadIdx.x, y = threadIdx.y;   // 32 x 8
    #pragma unroll
    for (int j = 0; j < 4; j++)
        t[y + 8 * j][x] = attn_w[(size_t)(nb + y + 8 * j) * (2 * H_DIM) + H_DIM + hb + x];
    __syncthreads();
    #pragma unroll
    for (int j = 0; j < 4; j++) {
        int h = hb + y + 8 * j;
        int n = nb + x;
        int p = (h >> 3) * 4 + (h & 3);
        int sel = (h >> 2) & 1;
        g_WeB[((size_t)p * H_DIM + n) * 2 + sel] = __uint_as_float(f2tf32(t[x][y + 8 * j]));
    }
}

// ---------------- kernel 0: init output (ctx half = 0, hidden half copy) --------
__global__ void init_kernel(const float* __restrict__ hidden, float* __restrict__ out) {
    int idx = blockIdx.x * 256 + threadIdx.x;          // 0..65535
    int b = idx >> 11;
    int c = idx & 2047;
    out[idx] = (c < H_DIM) ? 0.0f : hidden[b * H_DIM + (c - H_DIM)];
}

// ---------------- kernel 1: c[b,k] = hidden @ Wh^T + attn_b ----------------
// grid (128 k-chunks, 4 b-groups), block 256 (8 warps). Warp = one k, 8 batches.
__global__ void cvec_kernel(const float* __restrict__ hidden,
                            const float* __restrict__ attn_w,
                            const float* __restrict__ attn_b) {
    __shared__ float hdS[8][H_DIM];
    const int tid = threadIdx.x;
    const int wid = tid >> 5, lane = tid & 31;
    const int k = blockIdx.x * 8 + wid;
    const int b0 = blockIdx.y * 8;
    for (int i = tid; i < 8 * H_DIM; i += 256)
        hdS[i >> 10][i & (H_DIM - 1)] = hidden[(size_t)b0 * H_DIM + i];
    const float* wrow = attn_w + (size_t)k * (2 * H_DIM);   // Wh row k
    float wv[32];
    #pragma unroll
    for (int j = 0; j < 32; j++) wv[j] = wrow[lane + 32 * j];
    float bias = attn_b[k];
    __syncthreads();
    #pragma unroll
    for (int bi = 0; bi < 8; bi++) {
        float s = 0.0f;
        #pragma unroll
        for (int j = 0; j < 32; j++) s = fmaf(wv[j], hdS[bi][lane + 32 * j], s);
        #pragma unroll
        for (int o = 16; o > 0; o >>= 1) s += __shfl_xor_sync(0xffffffffu, s, o);
        if (lane == 0) g_c[(size_t)(b0 + bi) * H_DIM + k] = s + bias;
    }
}

// ---------------- kernel 2: fused tf32 mma.sync GEMM + tanh + v-dot ----------------
// CTA tile: M=128 x N=128, K=1024 (32 iters of KC=32). 4 warps 2x2, tile 64x64.
// 2 CTAs/SM. 3-slot cp.async ring + mbarrier full/empty pipeline.
// B fragments loaded BEFORE A ldmatrix in each ks block (latency ordering).
static constexpr int NKITER = 32;
static constexpr int W_C    = 0;      // words
static constexpr int W_V    = 128;
static constexpr int W_BARS = 256;    // 6 mbarriers: full[0..2], empty[0..2]
static constexpr int W_A    = 272;
static constexpr int STAGE_WORDS = 4096 + 4096;     // 8192
static constexpr int GEMM_SMEM_BYTES = (W_A + 3 * STAGE_WORDS) * 4;   // 99,392

__device__ __forceinline__ uint32_t full_bar(uint32_t smem_base, int s) {
    return smem_base + (W_BARS + 2 * s) * 4;
}
__device__ __forceinline__ uint32_t empty_bar(uint32_t smem_base, int s) {
    return smem_base + (W_BARS + 6 + 2 * s) * 4;
}

__device__ __forceinline__ void load_stage(uint32_t smem_base, int slot,
                                           const float* __restrict__ enc,
                                           const float2* __restrict__ WeB2,
                                           int row0, int kg0, int it, int tid) {
    const int base_w = W_A + slot * STAGE_WORDS;
    const int hbase = it * 32;
    // A: 128 rows x 32 words = 1024 16B chunks, 8 per thread (128 threads)
    #pragma unroll
    for (int j = 0; j < 8; j++) {
        int c = tid + j * 128;
        int m = c >> 3, k0 = (c & 7) * 4;
        uint32_t w = (uint32_t)(base_w + m * 32 + (k0 ^ ((m & 7) * 4)));
        CP_ASYNC16(smem_base + w * 4, enc + (size_t)(row0 + m) * H_DIM + hbase + k0);
    }
    // B: 16 pair-rows x 128 float2 = 1024 16B chunks, 8 per thread
    #pragma unroll
    for (int j = 0; j < 8; j++) {
        int c = tid + j * 128;
        int prow = c >> 6, n0 = (c & 63) * 2;     // float2 index, 2 per chunk
        uint32_t f2i = (uint32_t)(prow * 128 + (n0 ^ (4 * (prow & 3))));
        uint32_t w = (uint32_t)(base_w + 4096) + f2i * 2;
        CP_ASYNC16(smem_base + w * 4,
                   WeB2 + (size_t)(it * 16 + prow) * H_DIM + kg0 + n0);
    }
}

__global__ void __launch_bounds__(128, 2)
gemm_scores_kernel(const float* __restrict__ enc,
                   const float* __restrict__ v_w) {
    extern __shared__ float smw[];
    uint32_t smem_base = smem_u32(smw);
    const int tid = threadIdx.x;
    const int wid = tid >> 5, lane = tid & 31;
    const int q = lane >> 2, t4 = lane & 3;
    const int wm = wid & 1, wn = wid >> 1;          // 2 x 2 warp grid
    const int row0 = blockIdx.y * 128;              // row-block (slow axis)
    const int b = row0 >> 11;
    const int nc = blockIdx.x;                      // n-chunk (fast axis -> L2 A reuse)
    const int kg0 = nc * 128;

    const float2* __restrict__ WeB2 = reinterpret_cast<const float2*>(g_WeB);

    if (tid == 0) {
        #pragma unroll
        for (int s = 0; s < 3; s++) {
            MBARRIER_INIT(full_bar(smem_base, s), 128);
            MBARRIER_INIT(empty_bar(smem_base, s), 128);
        }
    }
    smw[W_C + tid] = g_c[b * H_DIM + kg0 + tid];
    smw[W_V + tid] = v_w[kg0 + tid];
    __syncthreads();

    // prologue: stages 0,1 into slots 0,1 (slots fresh -> no empty wait)
    load_stage(smem_base, 0, enc, WeB2, row0, kg0, 0, tid);
    CP_ASYNC_MBAR_ARRIVE(full_bar(smem_base, 0));
    load_stage(smem_base, 1, enc, WeB2, row0, kg0, 1, tid);
    CP_ASYNC_MBAR_ARRIVE(full_bar(smem_base, 1));

    // accumulators: 4 m-tiles x 8 n-tiles x 4 regs = 128
    float d[4][8][4];
    #pragma unroll
    for (int mt = 0; mt < 4; mt++)
        #pragma unroll
        for (int nt = 0; nt < 8; nt++)
            #pragma unroll
            for (int r = 0; r < 4; r++) d[mt][nt][r] = 0.0f;

    for (int it = 0; it < NKITER; it++) {
        const int slot = it % 3;
        MBARRIER_WAIT_PARITY(full_bar(smem_base, slot), (it / 3) & 1);

        const int bufA = W_A + slot * STAGE_WORDS;
        const float2* bufB = reinterpret_cast<const float2*>(smw + bufA + 4096);

        #pragma unroll
        for (int ks = 0; ks < 4; ks++) {
            // B fragments first (LDS 29-cyc latency covered by A ldmatrix issue)
            const int prow_l = ks * 4 + t4;
            uint32_t bb[8][2];
            #pragma unroll
            for (int nt = 0; nt < 8; nt++) {
                int col = wn * 64 + nt * 8 + q;
                float2 v = bufB[prow_l * 128 + (col ^ (4 * t4))];
                bb[nt][0] = __float_as_uint(v.x);
                bb[nt][1] = __float_as_uint(v.y);
            }
            // A fragments: one ldmatrix.x4 per mt
            uint32_t a[4][4];
            #pragma unroll
            for (int mt = 0; mt < 4; mt++) {
                int m = wm * 64 + mt * 16 + (lane & 15);
                int chk = ks * 2 + (lane >> 4);            // 16B chunk index in row
                uint32_t w = (uint32_t)(bufA + m * 32 + ((chk * 4) ^ ((m & 7) * 4)));
                uint32_t addr = smem_base + w * 4;
                asm volatile(
                    "ldmatrix.sync.aligned.m8n8.x4.shared.b16 {%0,%1,%2,%3}, [%4];"
                    : "=r"(a[mt][0]), "=r"(a[mt][1]), "=r"(a[mt][2]), "=r"(a[mt][3])
                    : "r"(addr));
            }
            #pragma unroll
            for (int mt = 0; mt < 4; mt++)
                #pragma unroll
                for (int nt = 0; nt < 8; nt++)
                    mma_tf32(d[mt][nt], a[mt], bb[nt]);

            // prefetch stage it+2 into slot (it+2)%3 after ks=0's MMAs
            if (ks == 0 && it + 2 < NKITER) {
                const int pslot = (it + 2) % 3;
                if (it >= 1) {
                    MBARRIER_WAIT_PARITY(empty_bar(smem_base, pslot), ((it - 1) / 3) & 1);
                }
                load_stage(smem_base, pslot, enc, WeB2, row0, kg0, it + 2, tid);
                CP_ASYNC_MBAR_ARRIVE(full_bar(smem_base, pslot));
            }
        }
        MBARRIER_ARRIVE(empty_bar(smem_base, slot));
    }

    // Epilogue: partial[plane][r] = sum_{n in warp's half} v[n]*tanh(d + c[n])
    #pragma unroll
    for (int mt = 0; mt < 4; mt++) {
        float s0 = 0.0f, s1 = 0.0f;
        #pragma unroll
        for (int nt = 0; nt < 8; nt++) {
            int n = wn * 64 + nt * 8 + t4 * 2;
            float c0 = smw[W_C + n], c1 = smw[W_C + n + 1];
            float v0 = smw[W_V + n], v1 = smw[W_V + n + 1];
            s0 = fmaf(tanh_fast(d[mt][nt][0] + c0), v0, s0);
            s0 = fmaf(tanh_fast(d[mt][nt][1] + c1), v1, s0);
            s1 = fmaf(tanh_fast(d[mt][nt][2] + c0), v0, s1);
            s1 = fmaf(tanh_fast(d[mt][nt][3] + c1), v1, s1);
        }
        #pragma unroll
        for (int o = 1; o < 4; o <<= 1) {
            s0 += __shfl_xor_sync(0xffffffffu, s0, o);
            s1 += __shfl_xor_sync(0xffffffffu, s1, o);
        }
        if (t4 == 0) {
            int r = row0 + wm * 64 + mt * 16 + q;
            size_t plane = (size_t)(nc * 2 + wn) * NROWS;
            g_part[plane + r] = s0;
            g_part[plane + r + 8] = s1;
        }
    }
}

// ---------------- kernel 3: fold partials + softmax over S per batch ----------------
__global__ void softmax_kernel(float* __restrict__ outw) {
    __shared__ float sh[S_DIM];
    __shared__ float red[256];
    int b = blockIdx.x, tid = threadIdx.x;
    float lmax = -1e30f;
    for (int i = tid; i < S_DIM; i += 256) {
        float v = 0.0f;
        #pragma unroll
        for (int p = 0; p < 16; p++) v += g_part[(size_t)p * NROWS + b * S_DIM + i];
        sh[i] = v;
        lmax = fmaxf(lmax, v);
    }
    red[tid] = lmax;
    __syncthreads();
    for (int s = 128; s > 0; s >>= 1) {
        if (tid < s) red[tid] = fmaxf(red[tid], red[tid + s]);
        __syncthreads();
    }
    float m = red[0];
    __syncthreads();
    float lsum = 0.0f;
    for (int i = tid; i < S_DIM; i += 256) {
        float e = expf(sh[i] - m);
        sh[i] = e;
        lsum += e;
    }
    red[tid] = lsum;
    __syncthreads();
    for (int s = 128; s > 0; s >>= 1) {
        if (tid < s) red[tid] += red[tid + s];
        __syncthreads();
    }
    float inv = 1.0f / red[0];
    for (int i = tid; i < S_DIM; i += 256) outw[b * S_DIM + i] = sh[i] * inv;
}

// ---------------- kernel 4: context[b,h] = sum_s w[b,s] * enc[b,s,h] ----------------
__global__ void context_kernel(const float* __restrict__ enc,
                               const float* __restrict__ w,
                               float* __restrict__ out) {
    __shared__ float ws[128];
    int b = blockIdx.x, sc = blockIdx.y, tid = threadIdx.x;
    if (tid < 128) ws[tid] = w[b * S_DIM + sc * 128 + tid];
    __syncthreads();
    const float4* e4 = reinterpret_cast<const float4*>(
        enc + ((size_t)(b * S_DIM + sc * 128)) * H_DIM);
    float ax = 0.f, ay = 0.f, az = 0.f, aw = 0.f;
    #pragma unroll 4
    for (int s = 0; s < 128; s++) {
        float wv = ws[s];
        float4 ev = e4[(size_t)s * 256 + tid];
        ax += wv * ev.x; ay += wv * ev.y; az += wv * ev.z; aw += wv * ev.w;
    }
    float* o = out + b * (2 * H_DIM) + tid * 4;
    atomicAdd(o + 0, ax);
    atomicAdd(o + 1, ay);
    atomicAdd(o + 2, az);
    atomicAdd(o + 3, aw);
}

// ---------------- launcher ----------------
extern "C" void kernel_launch(void* const* d_in, const int* in_sizes, int n_in,
                              void* d_out, int out_size) {
    const float* hidden = (const float*)d_in[0];   // (32, 1024)
    const float* enc    = (const float*)d_in[1];   // (32, 2048, 1024)
    const float* attn_w = (const float*)d_in[2];   // (1024, 2048)
    const float* attn_b = (const float*)d_in[3];   // (1024,)
    const float* v_w    = (const float*)d_in[4];   // (1, 1024)
    float* out = (float*)d_out;                    // [output (32,2048) | attn_w (32,2048,1)]

    cudaFuncSetAttribute(gemm_scores_kernel,
                         cudaFuncAttributeMaxDynamicSharedMemorySize,
                         GEMM_SMEM_BYTES);

    transpose_we_kernel<<<dim3(32, 32), dim3(32, 8)>>>(attn_w);
    init_kernel<<<256, 256>>>(hidden, out);
    cvec_kernel<<<dim3(128, 4), 256>>>(hidden, attn_w, attn_b);
    gemm_scores_kernel<<<dim3(8, 512), 128, GEMM_SMEM_BYTES>>>(enc, v_w);
    softmax_kernel<<<32, 256>>>(out + B_DIM * S_DIM);
    context_kernel<<<dim3(32, 16), 256>>>(enc, out + B_DIM * S_DIM, out);
}

// round 15
// speedup vs baseline: 1.0275x; 1.0097x over previous
#include <cuda_runtime.h>
#include <cstdint>

// Problem dims
#define B_DIM 32
#define S_DIM 2048
#define H_DIM 1024
#define NROWS (B_DIM * S_DIM)   // 65536

// ---------------- device scratch (no allocs allowed) ----------------
__device__ float g_part[16 * NROWS];               // partial scores: 16 planes (nc,wn)
__device__ float g_c[B_DIM * H_DIM];               // hW[b,k] + attn_b[k]
// We pair-packed + tf32-rounded: pair-row p = (h>>3)*4 + (h&3), sel = (h>>2)&1
//   g_WeB[(p*1024 + n)*2 + sel] = rna_tf32(We[n][h])   (float2 {B[k][n], B[k+4][n]})
__device__ float g_WeB[H_DIM * H_DIM];

// ---------------- helpers ----------------
__device__ __forceinline__ uint32_t smem_u32(const void* p) {
    uint32_t a;
    asm("{ .reg .u64 t; cvta.to.shared.u64 t, %1; cvt.u32.u64 %0, t; }"
        : "=r"(a) : "l"(p));
    return a;
}

__device__ __forceinline__ uint32_t f2tf32(float f) {
    uint32_t u;
    asm("cvt.rna.tf32.f32 %0, %1;" : "=r"(u) : "f"(f));
    return u;
}

// single-MUFU tanh (max err ~2^-11; fine vs 1e-3 gate with 1.9e-4 base)
__device__ __forceinline__ float tanh_fast(float x) {
    float y;
    asm("tanh.approx.f32 %0, %1;" : "=f"(y) : "f"(x));
    return y;
}

#define CP_ASYNC16(dst_u32, src_ptr) \
    asm volatile("cp.async.cg.shared.global [%0], [%1], 16;" \
                 :: "r"(dst_u32), "l"(src_ptr) : "memory")

// mbarrier ops
#define MBARRIER_INIT(mbar, count) \
    asm volatile("mbarrier.init.shared.b64 [%0], %1;" \
                 :: "r"((uint32_t)(mbar)), "r"((uint32_t)(count)) : "memory")

#define MBARRIER_ARRIVE(mbar) \
    asm volatile("mbarrier.arrive.shared.b64 _, [%0];" \
                 :: "r"((uint32_t)(mbar)) : "memory")

// arrive fires when this thread's prior cp.asyncs have completed (no count inc)
#define CP_ASYNC_MBAR_ARRIVE(mbar) \
    asm volatile("cp.async.mbarrier.arrive.noinc.shared.b64 [%0];" \
                 :: "r"((uint32_t)(mbar)) : "memory")

#define MBARRIER_WAIT_PARITY(mbar_smem_addr, phase_parity) do { \
    uint32_t _mbar = (uint32_t)(mbar_smem_addr); \
    uint32_t _parity = (uint32_t)(phase_parity); \
    uint32_t _done; \
    asm volatile( \
        "{\n\t" \
        ".reg .pred p;\n\t" \
        "mbarrier.try_wait.parity.acquire.cta.shared::cta.b64 p, [%1], %2;\n\t" \
        "selp.b32 %0, 1, 0, p;\n\t" \
        "}" \
        : "=r"(_done) : "r"(_mbar), "r"(_parity) : "memory"); \
    if (!_done) { \
        asm volatile( \
            "{\n\t" \
            ".reg .pred P1;\n\t" \
            "WAIT_LOOP_%=:\n\t" \
            "mbarrier.try_wait.parity.acquire.cta.shared::cta.b64 P1, [%0], %1, 0x989680;\n\t" \
            "@P1 bra.uni WAIT_DONE_%=;\n\t" \
            "bra.uni WAIT_LOOP_%=;\n\t" \
            "WAIT_DONE_%=:\n\t" \
            "}" \
            :: "r"(_mbar), "r"(_parity) : "memory"); \
    } \
} while (0)

__device__ __forceinline__ void mma_tf32(float d[4], const uint32_t a[4],
                                         const uint32_t b[2]) {
    asm volatile(
        "mma.sync.aligned.m16n8k8.row.col.f32.tf32.tf32.f32 "
        "{%0,%1,%2,%3}, {%4,%5,%6,%7}, {%8,%9}, {%0,%1,%2,%3};"
        : "+f"(d[0]), "+f"(d[1]), "+f"(d[2]), "+f"(d[3])
        : "r"(a[0]), "r"(a[1]), "r"(a[2]), "r"(a[3]), "r"(b[0]), "r"(b[1]));
}

// ---------------- fused pre-kernel: transpose_we + init + cvec -------------------
// grid 1792 x 256 threads, branch on blockIdx.x:
//   [0, 1024)    : transpose + tf32-round + pair-pack We (32 x 32 tile blocks)
//   [1024, 1280) : init output (ctx half = 0, hidden half copy)
//   [1280, 1792) : cvec (128 k-chunks x 4 b-groups)
__global__ void pre_kernel(const float* __restrict__ hidden,
                           const float* __restrict__ attn_w,
                           const float* __restrict__ attn_b,
                           float* __restrict__ out) {
    const int bx = blockIdx.x;
    const int tid = threadIdx.x;

    if (bx < 1024) {
        // ---- transpose We ----
        __shared__ float t[32][33];
        int nb = (bx & 31) * 32, hb = (bx >> 5) * 32;
        int x = tid & 31, y = tid >> 5;   // 32 x 8
        #pragma unroll
        for (int j = 0; j < 4; j++)
            t[y + 8 * j][x] = attn_w[(size_t)(nb + y + 8 * j) * (2 * H_DIM) + H_DIM + hb + x];
        __syncthreads();
        #pragma unroll
        for (int j = 0; j < 4; j++) {
            int h = hb + y + 8 * j;
            int n = nb + x;
            int p = (h >> 3) * 4 + (h & 3);
            int sel = (h >> 2) & 1;
            g_WeB[((size_t)p * H_DIM + n) * 2 + sel] =
                __uint_as_float(f2tf32(t[x][y + 8 * j]));
        }
    } else if (bx < 1280) {
        // ---- init output ----
        int idx = (bx - 1024) * 256 + tid;             // 0..65535
        int b = idx >> 11;
        int c = idx & 2047;
        out[idx] = (c < H_DIM) ? 0.0f : hidden[b * H_DIM + (c - H_DIM)];
    } else {
        // ---- cvec: c[b,k] = hidden @ Wh^T + attn_b ----
        __shared__ float hdS[8][H_DIM];
        const int bc = bx - 1280;                      // 0..511
        const int wid = tid >> 5, lane = tid & 31;
        const int k = (bc & 127) * 8 + wid;
        const int b0 = (bc >> 7) * 8;
        for (int i = tid; i < 8 * H_DIM; i += 256)
            hdS[i >> 10][i & (H_DIM - 1)] = hidden[(size_t)b0 * H_DIM + i];
        const float* wrow = attn_w + (size_t)k * (2 * H_DIM);   // Wh row k
        float wv[32];
        #pragma unroll
        for (int j = 0; j < 32; j++) wv[j] = wrow[lane + 32 * j];
        float bias = attn_b[k];
        __syncthreads();
        #pragma unroll
        for (int bi = 0; bi < 8; bi++) {
            float s = 0.0f;
            #pragma unroll
            for (int j = 0; j < 32; j++) s = fmaf(wv[j], hdS[bi][lane + 32 * j], s);
            #pragma unroll
            for (int o = 16; o > 0; o >>= 1) s += __shfl_xor_sync(0xffffffffu, s, o);
            if (lane == 0) g_c[(size_t)(b0 + bi) * H_DIM + k] = s + bias;
        }
    }
}

// ---------------- kernel 2: fused tf32 mma.sync GEMM + tanh + v-dot ----------------
// CTA tile: M=128 x N=128, K=1024 (32 iters of KC=32). 4 warps 2x2, tile 64x64.
// 2 CTAs/SM. 3-slot cp.async ring + mbarrier full/empty pipeline.
// B fragments loaded BEFORE A ldmatrix in each ks block (latency ordering).
static constexpr int NKITER = 32;
static constexpr int W_C    = 0;      // words
static constexpr int W_V    = 128;
static constexpr int W_BARS = 256;    // 6 mbarriers: full[0..2], empty[0..2]
static constexpr int W_A    = 272;
static constexpr int STAGE_WORDS = 4096 + 4096;     // 8192
static constexpr int GEMM_SMEM_BYTES = (W_A + 3 * STAGE_WORDS) * 4;   // 99,392

__device__ __forceinline__ uint32_t full_bar(uint32_t smem_base, int s) {
    return smem_base + (W_BARS + 2 * s) * 4;
}
__device__ __forceinline__ uint32_t empty_bar(uint32_t smem_base, int s) {
    return smem_base + (W_BARS + 6 + 2 * s) * 4;
}

__device__ __forceinline__ void load_stage(uint32_t smem_base, int slot,
                                           const float* __restrict__ enc,
                                           const float2* __restrict__ WeB2,
                                           int row0, int kg0, int it, int tid) {
    const int base_w = W_A + slot * STAGE_WORDS;
    const int hbase = it * 32;
    // A: 128 rows x 32 words = 1024 16B chunks, 8 per thread (128 threads)
    #pragma unroll
    for (int j = 0; j < 8; j++) {
        int c = tid + j * 128;
        int m = c >> 3, k0 = (c & 7) * 4;
        uint32_t w = (uint32_t)(base_w + m * 32 + (k0 ^ ((m & 7) * 4)));
        CP_ASYNC16(smem_base + w * 4, enc + (size_t)(row0 + m) * H_DIM + hbase + k0);
    }
    // B: 16 pair-rows x 128 float2 = 1024 16B chunks, 8 per thread
    #pragma unroll
    for (int j = 0; j < 8; j++) {
        int c = tid + j * 128;
        int prow = c >> 6, n0 = (c & 63) * 2;     // float2 index, 2 per chunk
        uint32_t f2i = (uint32_t)(prow * 128 + (n0 ^ (4 * (prow & 3))));
        uint32_t w = (uint32_t)(base_w + 4096) + f2i * 2;
        CP_ASYNC16(smem_base + w * 4,
                   WeB2 + (size_t)(it * 16 + prow) * H_DIM + kg0 + n0);
    }
}

__global__ void __launch_bounds__(128, 2)
gemm_scores_kernel(const float* __restrict__ enc,
                   const float* __restrict__ v_w) {
    extern __shared__ float smw[];
    uint32_t smem_base = smem_u32(smw);
    const int tid = threadIdx.x;
    const int wid = tid >> 5, lane = tid & 31;
    const int q = lane >> 2, t4 = lane & 3;
    const int wm = wid & 1, wn = wid >> 1;          // 2 x 2 warp grid
    const int row0 = blockIdx.y * 128;              // row-block (slow axis)
    const int b = row0 >> 11;
    const int nc = blockIdx.x;                      // n-chunk (fast axis -> L2 A reuse)
    const int kg0 = nc * 128;

    const float2* __restrict__ WeB2 = reinterpret_cast<const float2*>(g_WeB);

    if (tid == 0) {
        #pragma unroll
        for (int s = 0; s < 3; s++) {
            MBARRIER_INIT(full_bar(smem_base, s), 128);
            MBARRIER_INIT(empty_bar(smem_base, s), 128);
        }
    }
    smw[W_C + tid] = g_c[b * H_DIM + kg0 + tid];
    smw[W_V + tid] = v_w[kg0 + tid];
    __syncthreads();

    // prologue: stages 0,1 into slots 0,1 (slots fresh -> no empty wait)
    load_stage(smem_base, 0, enc, WeB2, row0, kg0, 0, tid);
    CP_ASYNC_MBAR_ARRIVE(full_bar(smem_base, 0));
    load_stage(smem_base, 1, enc, WeB2, row0, kg0, 1, tid);
    CP_ASYNC_MBAR_ARRIVE(full_bar(smem_base, 1));

    // accumulators: 4 m-tiles x 8 n-tiles x 4 regs = 128
    float d[4][8][4];
    #pragma unroll
    for (int mt = 0; mt < 4; mt++)
        #pragma unroll
        for (int nt = 0; nt < 8; nt++)
            #pragma unroll
            for (int r = 0; r < 4; r++) d[mt][nt][r] = 0.0f;

    for (int it = 0; it < NKITER; it++) {
        const int slot = it % 3;
        MBARRIER_WAIT_PARITY(full_bar(smem_base, slot), (it / 3) & 1);

        const int bufA = W_A + slot * STAGE_WORDS;
        const float2* bufB = reinterpret_cast<const float2*>(smw + bufA + 4096);

        #pragma unroll
        for (int ks = 0; ks < 4; ks++) {
            // B fragments first (LDS 29-cyc latency covered by A ldmatrix issue)
            const int prow_l = ks * 4 + t4;
            uint32_t bb[8][2];
            #pragma unroll
            for (int nt = 0; nt < 8; nt++) {
                int col = wn * 64 + nt * 8 + q;
                float2 v = bufB[prow_l * 128 + (col ^ (4 * t4))];
                bb[nt][0] = __float_as_uint(v.x);
                bb[nt][1] = __float_as_uint(v.y);
            }
            // A fragments: one ldmatrix.x4 per mt
            uint32_t a[4][4];
            #pragma unroll
            for (int mt = 0; mt < 4; mt++) {
                int m = wm * 64 + mt * 16 + (lane & 15);
                int chk = ks * 2 + (lane >> 4);            // 16B chunk index in row
                uint32_t w = (uint32_t)(bufA + m * 32 + ((chk * 4) ^ ((m & 7) * 4)));
                uint32_t addr = smem_base + w * 4;
                asm volatile(
                    "ldmatrix.sync.aligned.m8n8.x4.shared.b16 {%0,%1,%2,%3}, [%4];"
                    : "=r"(a[mt][0]), "=r"(a[mt][1]), "=r"(a[mt][2]), "=r"(a[mt][3])
                    : "r"(addr));
            }
            #pragma unroll
            for (int mt = 0; mt < 4; mt++)
                #pragma unroll
                for (int nt = 0; nt < 8; nt++)
                    mma_tf32(d[mt][nt], a[mt], bb[nt]);

            // prefetch stage it+2 into slot (it+2)%3 after ks=0's MMAs
            if (ks == 0 && it + 2 < NKITER) {
                const int pslot = (it + 2) % 3;
                if (it >= 1) {
                    MBARRIER_WAIT_PARITY(empty_bar(smem_base, pslot), ((it - 1) / 3) & 1);
                }
                load_stage(smem_base, pslot, enc, WeB2, row0, kg0, it + 2, tid);
                CP_ASYNC_MBAR_ARRIVE(full_bar(smem_base, pslot));
            }
        }
        MBARRIER_ARRIVE(empty_bar(smem_base, slot));
    }

    // Epilogue: partial[plane][r] = sum_{n in warp's half} v[n]*tanh(d + c[n])
    #pragma unroll
    for (int mt = 0; mt < 4; mt++) {
        float s0 = 0.0f, s1 = 0.0f;
        #pragma unroll
        for (int nt = 0; nt < 8; nt++) {
            int n = wn * 64 + nt * 8 + t4 * 2;
            float c0 = smw[W_C + n], c1 = smw[W_C + n + 1];
            float v0 = smw[W_V + n], v1 = smw[W_V + n + 1];
            s0 = fmaf(tanh_fast(d[mt][nt][0] + c0), v0, s0);
            s0 = fmaf(tanh_fast(d[mt][nt][1] + c1), v1, s0);
            s1 = fmaf(tanh_fast(d[mt][nt][2] + c0), v0, s1);
            s1 = fmaf(tanh_fast(d[mt][nt][3] + c1), v1, s1);
        }
        #pragma unroll
        for (int o = 1; o < 4; o <<= 1) {
            s0 += __shfl_xor_sync(0xffffffffu, s0, o);
            s1 += __shfl_xor_sync(0xffffffffu, s1, o);
        }
        if (t4 == 0) {
            int r = row0 + wm * 64 + mt * 16 + q;
            size_t plane = (size_t)(nc * 2 + wn) * NROWS;
            g_part[plane + r] = s0;
            g_part[plane + r + 8] = s1;
        }
    }
}

// ---------------- kernel 3: fold partials + softmax over S per batch ----------------
// block 1024: fewer serial strided iterations (32-CTA grid is latency-bound)
__global__ void softmax_kernel(float* __restrict__ outw) {
    __shared__ float sh[S_DIM];
    __shared__ float red[1024];
    int b = blockIdx.x, tid = threadIdx.x;
    float lmax = -1e30f;
    for (int i = tid; i < S_DIM; i += 1024) {
        float v = 0.0f;
        #pragma unroll
        for (int p = 0; p < 16; p++) v += g_part[(size_t)p * NROWS + b * S_DIM + i];
        sh[i] = v;
        lmax = fmaxf(lmax, v);
    }
    red[tid] = lmax;
    __syncthreads();
    for (int s = 512; s > 0; s >>= 1) {
        if (tid < s) red[tid] = fmaxf(red[tid], red[tid + s]);
        __syncthreads();
    }
    float m = red[0];
    __syncthreads();
    float lsum = 0.0f;
    for (int i = tid; i < S_DIM; i += 1024) {
        float e = expf(sh[i] - m);
        sh[i] = e;
        lsum += e;
    }
    red[tid] = lsum;
    __syncthreads();
    for (int s = 512; s > 0; s >>= 1) {
        if (tid < s) red[tid] += red[tid + s];
        __syncthreads();
    }
    float inv = 1.0f / red[0];
    for (int i = tid; i < S_DIM; i += 1024) outw[b * S_DIM + i] = sh[i] * inv;
}

// ---------------- kernel 4: context[b,h] = sum_s w[b,s] * enc[b,s,h] ----------------
__global__ void context_kernel(const float* __restrict__ enc,
                               const float* __restrict__ w,
                               float* __restrict__ out) {
    __shared__ float ws[128];
    int b = blockIdx.x, sc = blockIdx.y, tid = threadIdx.x;
    if (tid < 128) ws[tid] = w[b * S_DIM + sc * 128 + tid];
    __syncthreads();
    const float4* e4 = reinterpret_cast<const float4*>(
        enc + ((size_t)(b * S_DIM + sc * 128)) * H_DIM);
    float ax = 0.f, ay = 0.f, az = 0.f, aw = 0.f;
    #pragma unroll 4
    for (int s = 0; s < 128; s++) {
        float wv = ws[s];
        float4 ev = e4[(size_t)s * 256 + tid];
        ax += wv * ev.x; ay += wv * ev.y; az += wv * ev.z; aw += wv * ev.w;
    }
    float* o = out + b * (2 * H_DIM) + tid * 4;
    atomicAdd(o + 0, ax);
    atomicAdd(o + 1, ay);
    atomicAdd(o + 2, az);
    atomicAdd(o + 3, aw);
}

// ---------------- launcher ----------------
extern "C" void kernel_launch(void* const* d_in, const int* in_sizes, int n_in,
                              void* d_out, int out_size) {
    const float* hidden = (const float*)d_in[0];   // (32, 1024)
    const float* enc    = (const float*)d_in[1];   // (32, 2048, 1024)
    const float* attn_w = (const float*)d_in[2];   // (1024, 2048)
    const float* attn_b = (const float*)d_in[3];   // (1024,)
    const float* v_w    = (const float*)d_in[4];   // (1, 1024)
    float* out = (float*)d_out;                    // [output (32,2048) | attn_w (32,2048,1)]

    cudaFuncSetAttribute(gemm_scores_kernel,
                         cudaFuncAttributeMaxDynamicSharedMemorySize,
                         GEMM_SMEM_BYTES);

    pre_kernel<<<1792, 256>>>(hidden, attn_w, attn_b, out);
    gemm_scores_kernel<<<dim3(8, 512), 128, GEMM_SMEM_BYTES>>>(enc, v_w);
    softmax_kernel<<<32, 1024>>>(out + B_DIM * S_DIM);
    context_kernel<<<dim3(32, 16), 256>>>(enc, out + B_DIM * S_DIM, out);
}

// round 16
// speedup vs baseline: 1.0391x; 1.0113x over previous
#include <cuda_runtime.h>
#include <cstdint>

// Problem dims
#define B_DIM 32
#define S_DIM 2048
#define H_DIM 1024
#define NROWS (B_DIM * S_DIM)   // 65536

// ---------------- device scratch (no allocs allowed) ----------------
__device__ float g_part[16 * NROWS];               // partial scores: 16 planes (nc,wn)
__device__ float g_c[B_DIM * H_DIM];               // hW[b,k] + attn_b[k]
// We pair-packed + tf32-rounded: pair-row p = (h>>3)*4 + (h&3), sel = (h>>2)&1
//   g_WeB[(p*1024 + n)*2 + sel] = rna_tf32(We[n][h])   (float2 {B[k][n], B[k+4][n]})
__device__ float g_WeB[H_DIM * H_DIM];

// ---------------- helpers ----------------
__device__ __forceinline__ uint32_t smem_u32(const void* p) {
    uint32_t a;
    asm("{ .reg .u64 t; cvta.to.shared.u64 t, %1; cvt.u32.u64 %0, t; }"
        : "=r"(a) : "l"(p));
    return a;
}

__device__ __forceinline__ uint32_t f2tf32(float f) {
    uint32_t u;
    asm("cvt.rna.tf32.f32 %0, %1;" : "=r"(u) : "f"(f));
    return u;
}

// single-MUFU tanh (max err ~2^-11; fine vs 1e-3 gate with 1.9e-4 base)
__device__ __forceinline__ float tanh_fast(float x) {
    float y;
    asm("tanh.approx.f32 %0, %1;" : "=f"(y) : "f"(x));
    return y;
}

#define CP_ASYNC16(dst_u32, src_ptr) \
    asm volatile("cp.async.cg.shared.global [%0], [%1], 16;" \
                 :: "r"(dst_u32), "l"(src_ptr) : "memory")

// mbarrier ops
#define MBARRIER_INIT(mbar, count) \
    asm volatile("mbarrier.init.shared.b64 [%0], %1;" \
                 :: "r"((uint32_t)(mbar)), "r"((uint32_t)(count)) : "memory")

#define MBARRIER_ARRIVE(mbar) \
    asm volatile("mbarrier.arrive.shared.b64 _, [%0];" \
                 :: "r"((uint32_t)(mbar)) : "memory")

// arrive fires when this thread's prior cp.asyncs have completed (no count inc)
#define CP_ASYNC_MBAR_ARRIVE(mbar) \
    asm volatile("cp.async.mbarrier.arrive.noinc.shared.b64 [%0];" \
                 :: "r"((uint32_t)(mbar)) : "memory")

#define MBARRIER_WAIT_PARITY(mbar_smem_addr, phase_parity) do { \
    uint32_t _mbar = (uint32_t)(mbar_smem_addr); \
    uint32_t _parity = (uint32_t)(phase_parity); \
    uint32_t _done; \
    asm volatile( \
        "{\n\t" \
        ".reg .pred p;\n\t" \
        "mbarrier.try_wait.parity.acquire.cta.shared::cta.b64 p, [%1], %2;\n\t" \
        "selp.b32 %0, 1, 0, p;\n\t" \
        "}" \
        : "=r"(_done) : "r"(_mbar), "r"(_parity) : "memory"); \
    if (!_done) { \
        asm volatile( \
            "{\n\t" \
            ".reg .pred P1;\n\t" \
            "WAIT_LOOP_%=:\n\t" \
            "mbarrier.try_wait.parity.acquire.cta.shared::cta.b64 P1, [%0], %1, 0x989680;\n\t" \
            "@P1 bra.uni WAIT_DONE_%=;\n\t" \
            "bra.uni WAIT_LOOP_%=;\n\t" \
            "WAIT_DONE_%=:\n\t" \
            "}" \
            :: "r"(_mbar), "r"(_parity) : "memory"); \
    } \
} while (0)

__device__ __forceinline__ void mma_tf32(float d[4], const uint32_t a[4],
                                         const uint32_t b[2]) {
    asm volatile(
        "mma.sync.aligned.m16n8k8.row.col.f32.tf32.tf32.f32 "
        "{%0,%1,%2,%3}, {%4,%5,%6,%7}, {%8,%9}, {%0,%1,%2,%3};"
        : "+f"(d[0]), "+f"(d[1]), "+f"(d[2]), "+f"(d[3])
        : "r"(a[0]), "r"(a[1]), "r"(a[2]), "r"(a[3]), "r"(b[0]), "r"(b[1]));
}

// ---------------- fused pre-kernel: transpose_we + init + cvec -------------------
// grid 1792 x 256 threads, branch on blockIdx.x:
//   [0, 1024)    : transpose + tf32-round + pair-pack We (32 x 32 tile blocks)
//   [1024, 1280) : init output (ctx half = 0, hidden half copy)
//   [1280, 1792) : cvec (128 k-chunks x 4 b-groups)
__global__ void pre_kernel(const float* __restrict__ hidden,
                           const float* __restrict__ attn_w,
                           const float* __restrict__ attn_b,
                           float* __restrict__ out) {
    const int bx = blockIdx.x;
    const int tid = threadIdx.x;

    if (bx < 1024) {
        // ---- transpose We ----
        __shared__ float t[32][33];
        int nb = (bx & 31) * 32, hb = (bx >> 5) * 32;
        int x = tid & 31, y = tid >> 5;   // 32 x 8
        #pragma unroll
        for (int j = 0; j < 4; j++)
            t[y + 8 * j][x] = attn_w[(size_t)(nb + y + 8 * j) * (2 * H_DIM) + H_DIM + hb + x];
        __syncthreads();
        #pragma unroll
        for (int j = 0; j < 4; j++) {
            int h = hb + y + 8 * j;
            int n = nb + x;
            int p = (h >> 3) * 4 + (h & 3);
            int sel = (h >> 2) & 1;
            g_WeB[((size_t)p * H_DIM + n) * 2 + sel] =
                __uint_as_float(f2tf32(t[x][y + 8 * j]));
        }
    } else if (bx < 1280) {
        // ---- init output ----
        int idx = (bx - 1024) * 256 + tid;             // 0..65535
        int b = idx >> 11;
        int c = idx & 2047;
        out[idx] = (c < H_DIM) ? 0.0f : hidden[b * H_DIM + (c - H_DIM)];
    } else {
        // ---- cvec: c[b,k] = hidden @ Wh^T + attn_b ----
        __shared__ float hdS[8][H_DIM];
        const int bc = bx - 1280;                      // 0..511
        const int wid = tid >> 5, lane = tid & 31;
        const int k = (bc & 127) * 8 + wid;
        const int b0 = (bc >> 7) * 8;
        for (int i = tid; i < 8 * H_DIM; i += 256)
            hdS[i >> 10][i & (H_DIM - 1)] = hidden[(size_t)b0 * H_DIM + i];
        const float* wrow = attn_w + (size_t)k * (2 * H_DIM);   // Wh row k
        float wv[32];
        #pragma unroll
        for (int j = 0; j < 32; j++) wv[j] = wrow[lane + 32 * j];
        float bias = attn_b[k];
        __syncthreads();
        #pragma unroll
        for (int bi = 0; bi < 8; bi++) {
            float s = 0.0f;
            #pragma unroll
            for (int j = 0; j < 32; j++) s = fmaf(wv[j], hdS[bi][lane + 32 * j], s);
            #pragma unroll
            for (int o = 16; o > 0; o >>= 1) s += __shfl_xor_sync(0xffffffffu, s, o);
            if (lane == 0) g_c[(size_t)(b0 + bi) * H_DIM + k] = s + bias;
        }
    }
}

// ---------------- kernel 2: fused tf32 mma.sync GEMM + tanh + v-dot ----------------
// CTA tile: M=128 x N=128, K=1024 (32 iters of KC=32). 4 warps 2x2, tile 64x64.
// 2 CTAs/SM. 3-slot cp.async ring + mbarrier full/empty pipeline.
// B fragments loaded BEFORE A ldmatrix in each ks block (latency ordering).
static constexpr int NKITER = 32;
static constexpr int W_C    = 0;      // words
static constexpr int W_V    = 128;
static constexpr int W_BARS = 256;    // 6 mbarriers: full[0..2], empty[0..2]
static constexpr int W_A    = 272;
static constexpr int STAGE_WORDS = 4096 + 4096;     // 8192
static constexpr int GEMM_SMEM_BYTES = (W_A + 3 * STAGE_WORDS) * 4;   // 99,392

__device__ __forceinline__ uint32_t full_bar(uint32_t smem_base, int s) {
    return smem_base + (W_BARS + 2 * s) * 4;
}
__device__ __forceinline__ uint32_t empty_bar(uint32_t smem_base, int s) {
    return smem_base + (W_BARS + 6 + 2 * s) * 4;
}

__device__ __forceinline__ void load_stage(uint32_t smem_base, int slot,
                                           const float* __restrict__ enc,
                                           const float2* __restrict__ WeB2,
                                           int row0, int kg0, int it, int tid) {
    const int base_w = W_A + slot * STAGE_WORDS;
    const int hbase = it * 32;
    // A: 128 rows x 32 words = 1024 16B chunks, 8 per thread (128 threads)
    #pragma unroll
    for (int j = 0; j < 8; j++) {
        int c = tid + j * 128;
        int m = c >> 3, k0 = (c & 7) * 4;
        uint32_t w = (uint32_t)(base_w + m * 32 + (k0 ^ ((m & 7) * 4)));
        CP_ASYNC16(smem_base + w * 4, enc + (size_t)(row0 + m) * H_DIM + hbase + k0);
    }
    // B: 16 pair-rows x 128 float2 = 1024 16B chunks, 8 per thread
    #pragma unroll
    for (int j = 0; j < 8; j++) {
        int c = tid + j * 128;
        int prow = c >> 6, n0 = (c & 63) * 2;     // float2 index, 2 per chunk
        uint32_t f2i = (uint32_t)(prow * 128 + (n0 ^ (4 * (prow & 3))));
        uint32_t w = (uint32_t)(base_w + 4096) + f2i * 2;
        CP_ASYNC16(smem_base + w * 4,
                   WeB2 + (size_t)(it * 16 + prow) * H_DIM + kg0 + n0);
    }
}

__global__ void __launch_bounds__(128, 2)
gemm_scores_kernel(const float* __restrict__ enc,
                   const float* __restrict__ v_w) {
    extern __shared__ float smw[];
    uint32_t smem_base = smem_u32(smw);
    const int tid = threadIdx.x;
    const int wid = tid >> 5, lane = tid & 31;
    const int q = lane >> 2, t4 = lane & 3;
    const int wm = wid & 1, wn = wid >> 1;          // 2 x 2 warp grid
    const int row0 = blockIdx.y * 128;              // row-block (slow axis)
    const int b = row0 >> 11;
    const int nc = blockIdx.x;                      // n-chunk (fast axis -> L2 A reuse)
    const int kg0 = nc * 128;

    const float2* __restrict__ WeB2 = reinterpret_cast<const float2*>(g_WeB);

    if (tid == 0) {
        #pragma unroll
        for (int s = 0; s < 3; s++) {
            MBARRIER_INIT(full_bar(smem_base, s), 128);
            MBARRIER_INIT(empty_bar(smem_base, s), 128);
        }
    }
    smw[W_C + tid] = g_c[b * H_DIM + kg0 + tid];
    smw[W_V + tid] = v_w[kg0 + tid];
    __syncthreads();

    // prologue: stages 0,1 into slots 0,1 (slots fresh -> no empty wait)
    load_stage(smem_base, 0, enc, WeB2, row0, kg0, 0, tid);
    CP_ASYNC_MBAR_ARRIVE(full_bar(smem_base, 0));
    load_stage(smem_base, 1, enc, WeB2, row0, kg0, 1, tid);
    CP_ASYNC_MBAR_ARRIVE(full_bar(smem_base, 1));

    // accumulators: 4 m-tiles x 8 n-tiles x 4 regs = 128
    float d[4][8][4];
    #pragma unroll
    for (int mt = 0; mt < 4; mt++)
        #pragma unroll
        for (int nt = 0; nt < 8; nt++)
            #pragma unroll
            for (int r = 0; r < 4; r++) d[mt][nt][r] = 0.0f;

    for (int it = 0; it < NKITER; it++) {
        const int slot = it % 3;
        MBARRIER_WAIT_PARITY(full_bar(smem_base, slot), (it / 3) & 1);

        const int bufA = W_A + slot * STAGE_WORDS;
        const float2* bufB = reinterpret_cast<const float2*>(smw + bufA + 4096);

        #pragma unroll
        for (int ks = 0; ks < 4; ks++) {
            // B fragments first (LDS 29-cyc latency covered by A ldmatrix issue)
            const int prow_l = ks * 4 + t4;
            uint32_t bb[8][2];
            #pragma unroll
            for (int nt = 0; nt < 8; nt++) {
                int col = wn * 64 + nt * 8 + q;
                float2 v = bufB[prow_l * 128 + (col ^ (4 * t4))];
                bb[nt][0] = __float_as_uint(v.x);
                bb[nt][1] = __float_as_uint(v.y);
            }
            // A fragments: one ldmatrix.x4 per mt
            uint32_t a[4][4];
            #pragma unroll
            for (int mt = 0; mt < 4; mt++) {
                int m = wm * 64 + mt * 16 + (lane & 15);
                int chk = ks * 2 + (lane >> 4);            // 16B chunk index in row
                uint32_t w = (uint32_t)(bufA + m * 32 + ((chk * 4) ^ ((m & 7) * 4)));
                uint32_t addr = smem_base + w * 4;
                asm volatile(
                    "ldmatrix.sync.aligned.m8n8.x4.shared.b16 {%0,%1,%2,%3}, [%4];"
                    : "=r"(a[mt][0]), "=r"(a[mt][1]), "=r"(a[mt][2]), "=r"(a[mt][3])
                    : "r"(addr));
            }
            #pragma unroll
            for (int mt = 0; mt < 4; mt++)
                #pragma unroll
                for (int nt = 0; nt < 8; nt++)
                    mma_tf32(d[mt][nt], a[mt], bb[nt]);

            // prefetch stage it+2 into slot (it+2)%3 after ks=0's MMAs
            if (ks == 0 && it + 2 < NKITER) {
                const int pslot = (it + 2) % 3;
                if (it >= 1) {
                    MBARRIER_WAIT_PARITY(empty_bar(smem_base, pslot), ((it - 1) / 3) & 1);
                }
                load_stage(smem_base, pslot, enc, WeB2, row0, kg0, it + 2, tid);
                CP_ASYNC_MBAR_ARRIVE(full_bar(smem_base, pslot));
            }
        }
        MBARRIER_ARRIVE(empty_bar(smem_base, slot));
    }

    // Epilogue: partial[plane][r] = sum_{n in warp's half} v[n]*tanh(d + c[n])
    #pragma unroll
    for (int mt = 0; mt < 4; mt++) {
        float s0 = 0.0f, s1 = 0.0f;
        #pragma unroll
        for (int nt = 0; nt < 8; nt++) {
            int n = wn * 64 + nt * 8 + t4 * 2;
            float c0 = smw[W_C + n], c1 = smw[W_C + n + 1];
            float v0 = smw[W_V + n], v1 = smw[W_V + n + 1];
            s0 = fmaf(tanh_fast(d[mt][nt][0] + c0), v0, s0);
            s0 = fmaf(tanh_fast(d[mt][nt][1] + c1), v1, s0);
            s1 = fmaf(tanh_fast(d[mt][nt][2] + c0), v0, s1);
            s1 = fmaf(tanh_fast(d[mt][nt][3] + c1), v1, s1);
        }
        #pragma unroll
        for (int o = 1; o < 4; o <<= 1) {
            s0 += __shfl_xor_sync(0xffffffffu, s0, o);
            s1 += __shfl_xor_sync(0xffffffffu, s1, o);
        }
        if (t4 == 0) {
            int r = row0 + wm * 64 + mt * 16 + q;
            size_t plane = (size_t)(nc * 2 + wn) * NROWS;
            g_part[plane + r] = s0;
            g_part[plane + r + 8] = s1;
        }
    }
}

// ---------------- kernel 3: fold partials + softmax over S per batch ----------------
// block 1024: fewer serial strided iterations (32-CTA grid is latency-bound)
__global__ void softmax_kernel(float* __restrict__ outw) {
    __shared__ float sh[S_DIM];
    __shared__ float red[1024];
    int b = blockIdx.x, tid = threadIdx.x;
    float lmax = -1e30f;
    for (int i = tid; i < S_DIM; i += 1024) {
        float v = 0.0f;
        #pragma unroll
        for (int p = 0; p < 16; p++) v += g_part[(size_t)p * NROWS + b * S_DIM + i];
        sh[i] = v;
        lmax = fmaxf(lmax, v);
    }
    red[tid] = lmax;
    __syncthreads();
    for (int s = 512; s > 0; s >>= 1) {
        if (tid < s) red[tid] = fmaxf(red[tid], red[tid + s]);
        __syncthreads();
    }
    float m = red[0];
    __syncthreads();
    float lsum = 0.0f;
    for (int i = tid; i < S_DIM; i += 1024) {
        float e = expf(sh[i] - m);
        sh[i] = e;
        lsum += e;
    }
    red[tid] = lsum;
    __syncthreads();
    for (int s = 512; s > 0; s >>= 1) {
        if (tid < s) red[tid] += red[tid + s];
        __syncthreads();
    }
    float inv = 1.0f / red[0];
    for (int i = tid; i < S_DIM; i += 1024) outw[b * S_DIM + i] = sh[i] * inv;
}

// ---------------- kernel 4: context[b,h] = sum_s w[b,s] * enc[b,s,h] ----------------
// streaming loads (__ldcs, zero reuse) + deeper unroll for MLP
__global__ void context_kernel(const float* __restrict__ enc,
                               const float* __restrict__ w,
                               float* __restrict__ out) {
    __shared__ float ws[128];
    int b = blockIdx.x, sc = blockIdx.y, tid = threadIdx.x;
    if (tid < 128) ws[tid] = w[b * S_DIM + sc * 128 + tid];
    __syncthreads();
    const float4* e4 = reinterpret_cast<const float4*>(
        enc + ((size_t)(b * S_DIM + sc * 128)) * H_DIM);
    float ax = 0.f, ay = 0.f, az = 0.f, aw = 0.f;
    #pragma unroll 8
    for (int s = 0; s < 128; s++) {
        float wv = ws[s];
        float4 ev = __ldcs(&e4[(size_t)s * 256 + tid]);
        ax = fmaf(wv, ev.x, ax); ay = fmaf(wv, ev.y, ay);
        az = fmaf(wv, ev.z, az); aw = fmaf(wv, ev.w, aw);
    }
    float* o = out + b * (2 * H_DIM) + tid * 4;
    atomicAdd(o + 0, ax);
    atomicAdd(o + 1, ay);
    atomicAdd(o + 2, az);
    atomicAdd(o + 3, aw);
}

// ---------------- launcher ----------------
extern "C" void kernel_launch(void* const* d_in, const int* in_sizes, int n_in,
                              void* d_out, int out_size) {
    const float* hidden = (const float*)d_in[0];   // (32, 1024)
    const float* enc    = (const float*)d_in[1];   // (32, 2048, 1024)
    const float* attn_w = (const float*)d_in[2];   // (1024, 2048)
    const float* attn_b = (const float*)d_in[3];   // (1024,)
    const float* v_w    = (const float*)d_in[4];   // (1, 1024)
    float* out = (float*)d_out;                    // [output (32,2048) | attn_w (32,2048,1)]

    cudaFuncSetAttribute(gemm_scores_kernel,
                         cudaFuncAttributeMaxDynamicSharedMemorySize,
                         GEMM_SMEM_BYTES);

    pre_kernel<<<1792, 256>>>(hidden, attn_w, attn_b, out);
    gemm_scores_kernel<<<dim3(8, 512), 128, GEMM_SMEM_BYTES>>>(enc, v_w);
    softmax_kernel<<<32, 1024>>>(out + B_DIM * S_DIM);
    context_kernel<<<dim3(32, 16), 256>>>(enc, out + B_DIM * S_DIM, out);
}

// round 17
// speedup vs baseline: 1.0433x; 1.0040x over previous
#include <cuda_runtime.h>
#include <cstdint>

// Problem dims
#define B_DIM 32
#define S_DIM 2048
#define H_DIM 1024
#define NROWS (B_DIM * S_DIM)   // 65536

// ---------------- device scratch (no allocs allowed) ----------------
__device__ float g_part[16 * NROWS];               // partial scores: 16 planes (nc,wn)
__device__ float g_c[B_DIM * H_DIM];               // hW[b,k] + attn_b[k]
// We pair-packed + tf32-rounded: pair-row p = (h>>3)*4 + (h&3), sel = (h>>2)&1
//   g_WeB[(p*1024 + n)*2 + sel] = rna_tf32(We[n][h])   (float2 {B[k][n], B[k+4][n]})
__device__ float g_WeB[H_DIM * H_DIM];

// ---------------- helpers ----------------
__device__ __forceinline__ uint32_t smem_u32(const void* p) {
    uint32_t a;
    asm("{ .reg .u64 t; cvta.to.shared.u64 t, %1; cvt.u32.u64 %0, t; }"
        : "=r"(a) : "l"(p));
    return a;
}

__device__ __forceinline__ uint32_t f2tf32(float f) {
    uint32_t u;
    asm("cvt.rna.tf32.f32 %0, %1;" : "=r"(u) : "f"(f));
    return u;
}

// single-MUFU tanh (max err ~2^-11; fine vs 1e-3 gate with 1.9e-4 base)
__device__ __forceinline__ float tanh_fast(float x) {
    float y;
    asm("tanh.approx.f32 %0, %1;" : "=f"(y) : "f"(x));
    return y;
}

#define CP_ASYNC16(dst_u32, src_ptr) \
    asm volatile("cp.async.cg.shared.global [%0], [%1], 16;" \
                 :: "r"(dst_u32), "l"(src_ptr) : "memory")

// mbarrier ops
#define MBARRIER_INIT(mbar, count) \
    asm volatile("mbarrier.init.shared.b64 [%0], %1;" \
                 :: "r"((uint32_t)(mbar)), "r"((uint32_t)(count)) : "memory")

#define MBARRIER_ARRIVE(mbar) \
    asm volatile("mbarrier.arrive.shared.b64 _, [%0];" \
                 :: "r"((uint32_t)(mbar)) : "memory")

// arrive fires when this thread's prior cp.asyncs have completed (no count inc)
#define CP_ASYNC_MBAR_ARRIVE(mbar) \
    asm volatile("cp.async.mbarrier.arrive.noinc.shared.b64 [%0];" \
                 :: "r"((uint32_t)(mbar)) : "memory")

#define MBARRIER_WAIT_PARITY(mbar_smem_addr, phase_parity) do { \
    uint32_t _mbar = (uint32_t)(mbar_smem_addr); \
    uint32_t _parity = (uint32_t)(phase_parity); \
    uint32_t _done; \
    asm volatile( \
        "{\n\t" \
        ".reg .pred p;\n\t" \
        "mbarrier.try_wait.parity.acquire.cta.shared::cta.b64 p, [%1], %2;\n\t" \
        "selp.b32 %0, 1, 0, p;\n\t" \
        "}" \
        : "=r"(_done) : "r"(_mbar), "r"(_parity) : "memory"); \
    if (!_done) { \
        asm volatile( \
            "{\n\t" \
            ".reg .pred P1;\n\t" \
            "WAIT_LOOP_%=:\n\t" \
            "mbarrier.try_wait.parity.acquire.cta.shared::cta.b64 P1, [%0], %1, 0x989680;\n\t" \
            "@P1 bra.uni WAIT_DONE_%=;\n\t" \
            "bra.uni WAIT_LOOP_%=;\n\t" \
            "WAIT_DONE_%=:\n\t" \
            "}" \
            :: "r"(_mbar), "r"(_parity) : "memory"); \
    } \
} while (0)

__device__ __forceinline__ void mma_tf32(float d[4], const uint32_t a[4],
                                         const uint32_t b[2]) {
    asm volatile(
        "mma.sync.aligned.m16n8k8.row.col.f32.tf32.tf32.f32 "
        "{%0,%1,%2,%3}, {%4,%5,%6,%7}, {%8,%9}, {%0,%1,%2,%3};"
        : "+f"(d[0]), "+f"(d[1]), "+f"(d[2]), "+f"(d[3])
        : "r"(a[0]), "r"(a[1]), "r"(a[2]), "r"(a[3]), "r"(b[0]), "r"(b[1]));
}

// ---------------- fused pre-kernel: transpose_we + init + cvec -------------------
__global__ void pre_kernel(const float* __restrict__ hidden,
                           const float* __restrict__ attn_w,
                           const float* __restrict__ attn_b,
                           float* __restrict__ out) {
    const int bx = blockIdx.x;
    const int tid = threadIdx.x;

    if (bx < 1024) {
        // ---- transpose We ----
        __shared__ float t[32][33];
        int nb = (bx & 31) * 32, hb = (bx >> 5) * 32;
        int x = tid & 31, y = tid >> 5;   // 32 x 8
        #pragma unroll
        for (int j = 0; j < 4; j++)
            t[y + 8 * j][x] = attn_w[(size_t)(nb + y + 8 * j) * (2 * H_DIM) + H_DIM + hb + x];
        __syncthreads();
        #pragma unroll
        for (int j = 0; j < 4; j++) {
            int h = hb + y + 8 * j;
            int n = nb + x;
            int p = (h >> 3) * 4 + (h & 3);
            int sel = (h >> 2) & 1;
            g_WeB[((size_t)p * H_DIM + n) * 2 + sel] =
                __uint_as_float(f2tf32(t[x][y + 8 * j]));
        }
    } else if (bx < 1280) {
        // ---- init output ----
        int idx = (bx - 1024) * 256 + tid;             // 0..65535
        int b = idx >> 11;
        int c = idx & 2047;
        out[idx] = (c < H_DIM) ? 0.0f : hidden[b * H_DIM + (c - H_DIM)];
    } else {
        // ---- cvec: c[b,k] = hidden @ Wh^T + attn_b ----
        __shared__ float hdS[8][H_DIM];
        const int bc = bx - 1280;                      // 0..511
        const int wid = tid >> 5, lane = tid & 31;
        const int k = (bc & 127) * 8 + wid;
        const int b0 = (bc >> 7) * 8;
        for (int i = tid; i < 8 * H_DIM; i += 256)
            hdS[i >> 10][i & (H_DIM - 1)] = hidden[(size_t)b0 * H_DIM + i];
        const float* wrow = attn_w + (size_t)k * (2 * H_DIM);   // Wh row k
        float wv[32];
        #pragma unroll
        for (int j = 0; j < 32; j++) wv[j] = wrow[lane + 32 * j];
        float bias = attn_b[k];
        __syncthreads();
        #pragma unroll
        for (int bi = 0; bi < 8; bi++) {
            float s = 0.0f;
            #pragma unroll
            for (int j = 0; j < 32; j++) s = fmaf(wv[j], hdS[bi][lane + 32 * j], s);
            #pragma unroll
            for (int o = 16; o > 0; o >>= 1) s += __shfl_xor_sync(0xffffffffu, s, o);
            if (lane == 0) g_c[(size_t)(b0 + bi) * H_DIM + k] = s + bias;
        }
    }
}

// ---------------- kernel 2: fused tf32 mma.sync GEMM + tanh + v-dot ----------------
// CTA tile: M=128 x N=128, K=1024 (32 iters of KC=32). 4 warps 2x2, tile 64x64.
// 2 CTAs/SM. 3-slot cp.async ring + mbarrier full/empty pipeline.
// Warp-level empty arrives (count 4); division-free slot/parity rotation.
static constexpr int NKITER = 32;
static constexpr int W_C    = 0;      // words
static constexpr int W_V    = 128;
static constexpr int W_BARS = 256;    // 6 mbarriers: full[0..2], empty[0..2]
static constexpr int W_A    = 272;
static constexpr int STAGE_WORDS = 4096 + 4096;     // 8192
static constexpr int GEMM_SMEM_BYTES = (W_A + 3 * STAGE_WORDS) * 4;   // 99,392

__device__ __forceinline__ uint32_t full_bar(uint32_t smem_base, int s) {
    return smem_base + (W_BARS + 2 * s) * 4;
}
__device__ __forceinline__ uint32_t empty_bar(uint32_t smem_base, int s) {
    return smem_base + (W_BARS + 6 + 2 * s) * 4;
}

__device__ __forceinline__ void load_stage(uint32_t smem_base, int slot,
                                           const float* __restrict__ enc,
                                           const float2* __restrict__ WeB2,
                                           int row0, int kg0, int it, int tid) {
    const int base_w = W_A + slot * STAGE_WORDS;
    const int hbase = it * 32;
    // A: 128 rows x 32 words = 1024 16B chunks, 8 per thread (128 threads)
    #pragma unroll
    for (int j = 0; j < 8; j++) {
        int c = tid + j * 128;
        int m = c >> 3, k0 = (c & 7) * 4;
        uint32_t w = (uint32_t)(base_w + m * 32 + (k0 ^ ((m & 7) * 4)));
        CP_ASYNC16(smem_base + w * 4, enc + (size_t)(row0 + m) * H_DIM + hbase + k0);
    }
    // B: 16 pair-rows x 128 float2 = 1024 16B chunks, 8 per thread
    #pragma unroll
    for (int j = 0; j < 8; j++) {
        int c = tid + j * 128;
        int prow = c >> 6, n0 = (c & 63) * 2;     // float2 index, 2 per chunk
        uint32_t f2i = (uint32_t)(prow * 128 + (n0 ^ (4 * (prow & 3))));
        uint32_t w = (uint32_t)(base_w + 4096) + f2i * 2;
        CP_ASYNC16(smem_base + w * 4,
                   WeB2 + (size_t)(it * 16 + prow) * H_DIM + kg0 + n0);
    }
}

__global__ void __launch_bounds__(128, 2)
gemm_scores_kernel(const float* __restrict__ enc,
                   const float* __restrict__ v_w) {
    extern __shared__ float smw[];
    uint32_t smem_base = smem_u32(smw);
    const int tid = threadIdx.x;
    const int wid = tid >> 5, lane = tid & 31;
    const int q = lane >> 2, t4 = lane & 3;
    const int wm = wid & 1, wn = wid >> 1;          // 2 x 2 warp grid
    const int row0 = blockIdx.y * 128;              // row-block (slow axis)
    const int b = row0 >> 11;
    const int nc = blockIdx.x;                      // n-chunk (fast axis -> L2 A reuse)
    const int kg0 = nc * 128;

    const float2* __restrict__ WeB2 = reinterpret_cast<const float2*>(g_WeB);

    if (tid == 0) {
        #pragma unroll
        for (int s = 0; s < 3; s++) {
            MBARRIER_INIT(full_bar(smem_base, s), 128);
            MBARRIER_INIT(empty_bar(smem_base, s), 4);   // warp-level arrives
        }
    }
    smw[W_C + tid] = g_c[b * H_DIM + kg0 + tid];
    smw[W_V + tid] = v_w[kg0 + tid];
    __syncthreads();

    // prologue: stages 0,1 into slots 0,1 (slots fresh -> no empty wait)
    load_stage(smem_base, 0, enc, WeB2, row0, kg0, 0, tid);
    CP_ASYNC_MBAR_ARRIVE(full_bar(smem_base, 0));
    load_stage(smem_base, 1, enc, WeB2, row0, kg0, 1, tid);
    CP_ASYNC_MBAR_ARRIVE(full_bar(smem_base, 1));

    // accumulators: 4 m-tiles x 8 n-tiles x 4 regs = 128
    float d[4][8][4];
    #pragma unroll
    for (int mt = 0; mt < 4; mt++)
        #pragma unroll
        for (int nt = 0; nt < 8; nt++)
            #pragma unroll
            for (int r = 0; r < 4; r++) d[mt][nt][r] = 0.0f;

    // division-free pipeline state:
    //   slot: consumer slot (it % 3), fullPh: parity of full[slot] (it/3)&1
    //   pslot: producer slot ((it+2)%3), emptyPh: parity of empty[pslot] ((it-1)/3)&1
    int slot = 0, fullPh = 0;
    int pslot = 2, emptyPh = 0;

    for (int it = 0; it < NKITER; it++) {
        MBARRIER_WAIT_PARITY(full_bar(smem_base, slot), fullPh);

        const int bufA = W_A + slot * STAGE_WORDS;
        const float2* bufB = reinterpret_cast<const float2*>(smw + bufA + 4096);

        #pragma unroll
        for (int ks = 0; ks < 4; ks++) {
            // B fragments first (LDS 29-cyc latency covered by A ldmatrix issue)
            const int prow_l = ks * 4 + t4;
            uint32_t bb[8][2];
            #pragma unroll
            for (int nt = 0; nt < 8; nt++) {
                int col = wn * 64 + nt * 8 + q;
                float2 v = bufB[prow_l * 128 + (col ^ (4 * t4))];
                bb[nt][0] = __float_as_uint(v.x);
                bb[nt][1] = __float_as_uint(v.y);
            }
            // A fragments: one ldmatrix.x4 per mt
            uint32_t a[4][4];
            #pragma unroll
            for (int mt = 0; mt < 4; mt++) {
                int m = wm * 64 + mt * 16 + (lane & 15);
                int chk = ks * 2 + (lane >> 4);            // 16B chunk index in row
                uint32_t w = (uint32_t)(bufA + m * 32 + ((chk * 4) ^ ((m & 7) * 4)));
                uint32_t addr = smem_base + w * 4;
                asm volatile(
                    "ldmatrix.sync.aligned.m8n8.x4.shared.b16 {%0,%1,%2,%3}, [%4];"
                    : "=r"(a[mt][0]), "=r"(a[mt][1]), "=r"(a[mt][2]), "=r"(a[mt][3])
                    : "r"(addr));
            }
            #pragma unroll
            for (int mt = 0; mt < 4; mt++)
                #pragma unroll
                for (int nt = 0; nt < 8; nt++)
                    mma_tf32(d[mt][nt], a[mt], bb[nt]);

            // prefetch stage it+2 into pslot after ks=0's MMAs
            if (ks == 0 && it + 2 < NKITER) {
                if (it >= 1) {
                    MBARRIER_WAIT_PARITY(empty_bar(smem_base, pslot), emptyPh);
                    if (pslot == 2) emptyPh ^= 1;      // (it-1)/3 parity flips after slot wrap
                }
                load_stage(smem_base, pslot, enc, WeB2, row0, kg0, it + 2, tid);
                CP_ASYNC_MBAR_ARRIVE(full_bar(smem_base, pslot));
            }
        }
        // done reading slot this iteration: one arrive per warp (count 4)
        if (lane == 0) MBARRIER_ARRIVE(empty_bar(smem_base, slot));

        // rotate consumer/producer slots without division
        if (++slot == 3) { slot = 0; fullPh ^= 1; }
        if (++pslot == 3) pslot = 0;
    }

    // Epilogue: partial[plane][r] = sum_{n in warp's half} v[n]*tanh(d + c[n])
    #pragma unroll
    for (int mt = 0; mt < 4; mt++) {
        float s0 = 0.0f, s1 = 0.0f;
        #pragma unroll
        for (int nt = 0; nt < 8; nt++) {
            int n = wn * 64 + nt * 8 + t4 * 2;
            float c0 = smw[W_C + n], c1 = smw[W_C + n + 1];
            float v0 = smw[W_V + n], v1 = smw[W_V + n + 1];
            s0 = fmaf(tanh_fast(d[mt][nt][0] + c0), v0, s0);
            s0 = fmaf(tanh_fast(d[mt][nt][1] + c1), v1, s0);
            s1 = fmaf(tanh_fast(d[mt][nt][2] + c0), v0, s1);
            s1 = fmaf(tanh_fast(d[mt][nt][3] + c1), v1, s1);
        }
        #pragma unroll
        for (int o = 1; o < 4; o <<= 1) {
            s0 += __shfl_xor_sync(0xffffffffu, s0, o);
            s1 += __shfl_xor_sync(0xffffffffu, s1, o);
        }
        if (t4 == 0) {
            int r = row0 + wm * 64 + mt * 16 + q;
            size_t plane = (size_t)(nc * 2 + wn) * NROWS;
            g_part[plane + r] = s0;
            g_part[plane + r + 8] = s1;
        }
    }
}

// ---------------- kernel 3: fold partials + softmax over S per batch ----------------
__global__ void softmax_kernel(float* __restrict__ outw) {
    __shared__ float sh[S_DIM];
    __shared__ float red[1024];
    int b = blockIdx.x, tid = threadIdx.x;
    float lmax = -1e30f;
    for (int i = tid; i < S_DIM; i += 1024) {
        float v = 0.0f;
        #pragma unroll
        for (int p = 0; p < 16; p++) v += g_part[(size_t)p * NROWS + b * S_DIM + i];
        sh[i] = v;
        lmax = fmaxf(lmax, v);
    }
    red[tid] = lmax;
    __syncthreads();
    for (int s = 512; s > 0; s >>= 1) {
        if (tid < s) red[tid] = fmaxf(red[tid], red[tid + s]);
        __syncthreads();
    }
    float m = red[0];
    __syncthreads();
    float lsum = 0.0f;
    for (int i = tid; i < S_DIM; i += 1024) {
        float e = expf(sh[i] - m);
        sh[i] = e;
        lsum += e;
    }
    red[tid] = lsum;
    __syncthreads();
    for (int s = 512; s > 0; s >>= 1) {
        if (tid < s) red[tid] += red[tid + s];
        __syncthreads();
    }
    float inv = 1.0f / red[0];
    for (int i = tid; i < S_DIM; i += 1024) outw[b * S_DIM + i] = sh[i] * inv;
}

// ---------------- kernel 4: context[b,h] = sum_s w[b,s] * enc[b,s,h] ----------------
__global__ void context_kernel(const float* __restrict__ enc,
                               const float* __restrict__ w,
                               float* __restrict__ out) {
    __shared__ float ws[128];
    int b = blockIdx.x, sc = blockIdx.y, tid = threadIdx.x;
    if (tid < 128) ws[tid] = w[b * S_DIM + sc * 128 + tid];
    __syncthreads();
    const float4* e4 = reinterpret_cast<const float4*>(
        enc + ((size_t)(b * S_DIM + sc * 128)) * H_DIM);
    float ax = 0.f, ay = 0.f, az = 0.f, aw = 0.f;
    #pragma unroll 8
    for (int s = 0; s < 128; s++) {
        float wv = ws[s];
        float4 ev = __ldcs(&e4[(size_t)s * 256 + tid]);
        ax = fmaf(wv, ev.x, ax); ay = fmaf(wv, ev.y, ay);
        az = fmaf(wv, ev.z, az); aw = fmaf(wv, ev.w, aw);
    }
    float* o = out + b * (2 * H_DIM) + tid * 4;
    atomicAdd(o + 0, ax);
    atomicAdd(o + 1, ay);
    atomicAdd(o + 2, az);
    atomicAdd(o + 3, aw);
}

// ---------------- launcher ----------------
extern "C" void kernel_launch(void* const* d_in, const int* in_sizes, int n_in,
                              void* d_out, int out_size) {
    const float* hidden = (const float*)d_in[0];   // (32, 1024)
    const float* enc    = (const float*)d_in[1];   // (32, 2048, 1024)
    const float* attn_w = (const float*)d_in[2];   // (1024, 2048)
    const float* attn_b = (const float*)d_in[3];   // (1024,)
    const float* v_w    = (const float*)d_in[4];   // (1, 1024)
    float* out = (float*)d_out;                    // [output (32,2048) | attn_w (32,2048,1)]

    cudaFuncSetAttribute(gemm_scores_kernel,
                         cudaFuncAttributeMaxDynamicSharedMemorySize,
                         GEMM_SMEM_BYTES);

    pre_kernel<<<1792, 256>>>(hidden, attn_w, attn_b, out);
    gemm_scores_kernel<<<dim3(8, 512), 128, GEMM_SMEM_BYTES>>>(enc, v_w);
    softmax_kernel<<<32, 1024>>>(out + B_DIM * S_DIM);
    context_kernel<<<dim3(32, 16), 256>>>(enc, out + B_DIM * S_DIM, out);
}